// round 13
// baseline (speedup 1.0000x reference)
#include <cuda_runtime.h>
#include <cuda_fp16.h>
#include <cstdint>
#include <math.h>

#define TSEQ 2048
#define NE   1024
#define NH   16
#define DKH  64
#define NB   2
#define MTOT (NB*TSEQ)   // 4096

// Scratch (allocation-free), fp16.
__device__ __half g_Xh[MTOT*NE];
__device__ __half g_Wh[4*NE*NE];    // q,k,v,o
__device__ __half g_Qh[MTOT*NE];    // Q pre-scaled by 0.125
__device__ __half g_Kh[MTOT*NE];
__device__ __half g_Vh[MTOT*NE];
__device__ __half g_Yh[MTOT*NE];    // attention out, pre-scaled by 64

// ---------------------------------------------------------------------------
static __device__ __forceinline__ uint32_t smem_u32(const void* p) {
    uint32_t a;
    asm("{ .reg .u64 t; cvta.to.shared.u64 t, %1; cvt.u32.u64 %0, t; }" : "=r"(a) : "l"(p));
    return a;
}
static __device__ __forceinline__ void ldsm_x4(uint32_t& r0, uint32_t& r1,
                                               uint32_t& r2, uint32_t& r3, uint32_t a) {
    asm volatile("ldmatrix.sync.aligned.m8n8.x4.shared.b16 {%0,%1,%2,%3}, [%4];"
                 : "=r"(r0), "=r"(r1), "=r"(r2), "=r"(r3) : "r"(a));
}
static __device__ __forceinline__ void ldsm_x4_t(uint32_t& r0, uint32_t& r1,
                                                 uint32_t& r2, uint32_t& r3, uint32_t a) {
    asm volatile("ldmatrix.sync.aligned.m8n8.x4.trans.shared.b16 {%0,%1,%2,%3}, [%4];"
                 : "=r"(r0), "=r"(r1), "=r"(r2), "=r"(r3) : "r"(a));
}
static __device__ __forceinline__ void mma16816(float* c, const uint32_t* a, const uint32_t* b) {
    asm volatile("mma.sync.aligned.m16n8k16.row.col.f32.f16.f16.f32 "
                 "{%0,%1,%2,%3}, {%4,%5,%6,%7}, {%8,%9}, {%0,%1,%2,%3};"
                 : "+f"(c[0]), "+f"(c[1]), "+f"(c[2]), "+f"(c[3])
                 : "r"(a[0]), "r"(a[1]), "r"(a[2]), "r"(a[3]), "r"(b[0]), "r"(b[1]));
}
#define CP_A16(dst, src) asm volatile("cp.async.cg.shared.global [%0], [%1], 16;" :: "r"(dst), "l"(src))
#define CP_COMMIT()      asm volatile("cp.async.commit_group;" ::: "memory")
#define CP_WAIT0()       asm volatile("cp.async.wait_group 0;" ::: "memory")
#define CP_WAIT1()       asm volatile("cp.async.wait_group 1;" ::: "memory")

static __device__ __forceinline__ uint32_t pack_h2(float x, float y) {
    union { __half2 b; uint32_t u; } p;
    p.b.x = __float2half_rn(x); p.b.y = __float2half_rn(y);
    return p.u;
}

// ---------------------------------------------------------------------------
// Fused pre-pass: x -> Xh; Wq,k,v,o -> Wh.
// ---------------------------------------------------------------------------
__global__ void split_all(const float* __restrict__ x,
                          const float* __restrict__ Wq, const float* __restrict__ Wk,
                          const float* __restrict__ Wv, const float* __restrict__ Wo,
                          __half* __restrict__ Xh, __half* __restrict__ WhB)
{
    const int bx = blockIdx.x;
    if (bx < 4096) {
        size_t i = (size_t)bx * 1024 + threadIdx.x * 4;
        float4 v = *(const float4*)(x + i);
        *(uint2*)(Xh + i) = make_uint2(pack_h2(v.x, v.y), pack_h2(v.z, v.w));
    } else {
        const int r = bx - 4096;
        const int w = r >> 10;
        const float* ws = (w == 0) ? Wq : (w == 1) ? Wk : (w == 2) ? Wv : Wo;
        size_t j = (size_t)(r & 1023) * 1024 + threadIdx.x * 4;
        float4 v = *(const float4*)(ws + j);
        *(uint2*)(WhB + (size_t)w * NE * NE + j) =
            make_uint2(pack_h2(v.x, v.y), pack_h2(v.z, v.w));
    }
}

// ---------------------------------------------------------------------------
// GEMM: C = A * Wh^T (1 term). CTA 128x128, 128 threads, warp tile 64x64
// (2x2 warps), kc=64, 2-stage cp.async gmem ring + fragment double-buffer.
// Row stride 144B (64 fp16 + 16B pad) -> conflict-free ldsm.
// MODE 0: fp16 out, scale (z==0 ? 0.125 : 1). MODE 1: fp32 out, *1/64 + bias.
// ---------------------------------------------------------------------------
#define GSTRIDE 144
#define G_T     (128 * GSTRIDE)          // 18432 per tile (A or W)
#define G_STAGE (2 * G_T)                // 36864 : A|W
#define GSMEM   (2 * G_STAGE)            // 73728
#define NKC     (NE / 64)                // 16

template<int MODE>
__global__ void __launch_bounds__(128, 2)
gemm64(const __half* __restrict__ Ah, const __half* __restrict__ WhB,
       const float* __restrict__ b0, const float* __restrict__ b1, const float* __restrict__ b2,
       __half* __restrict__ O0, __half* __restrict__ O1, __half* __restrict__ O2,
       float* __restrict__ Fout)
{
    extern __shared__ char smem[];
    const int tid  = threadIdx.x;
    const int wid  = tid >> 5;
    const int lane = tid & 31;
    const int z    = blockIdx.z;
    const __half* Wh = WhB + (size_t)z * NE * NE;
    const float* bias = (z == 0) ? b0 : (z == 1) ? b1 : b2;
    const int mbase = blockIdx.y * 128;
    const int nbase = blockIdx.x * 128;
    const uint32_t smb = smem_u32(smem);

    const int warp_m = wid >> 1;        // 0..1 -> 64 rows
    const int warp_n = wid & 1;         // 0..1 -> 64 cols
    const int la_row = warp_m * 64 + (lane & 15);
    const int la_k8  = ((lane >> 4) & 1) * 8;
    const int lw_row = warp_n * 64 + (lane & 7) + ((lane >> 4) & 1) * 8;
    const int lw_k8  = ((lane >> 3) & 1) * 8;

    const int lr = tid >> 3;       // 0..15
    const int lc = tid & 7;        // 0..7 -> 16B chunk

    float acc[4][8][4];
#pragma unroll
    for (int mi = 0; mi < 4; mi++)
#pragma unroll
        for (int nf = 0; nf < 8; nf++)
#pragma unroll
            for (int q = 0; q < 4; q++) acc[mi][nf][q] = 0.f;

#define LOAD_G(buf, kt) do {                                                  \
        uint32_t sb_ = smb + (buf) * G_STAGE;                                 \
        int kcol_ = (kt) * 64 + lc * 8;                                       \
        _Pragma("unroll")                                                     \
        for (int i = 0; i < 8; i++) {                                         \
            int r_ = lr + 16 * i;                                             \
            CP_A16(sb_ + r_ * GSTRIDE + lc * 16,                              \
                   (const char*)(Ah + (size_t)(mbase + r_) * NE + kcol_));    \
            CP_A16(sb_ + G_T + r_ * GSTRIDE + lc * 16,                        \
                   (const char*)(Wh + (size_t)(nbase + r_) * NE + kcol_));    \
        }                                                                     \
    } while (0)

// Load ldsm fragments for k-slice ks into buffer fb.
#define LOAD_FRAG(fb, base, ks) do {                                          \
        _Pragma("unroll")                                                     \
        for (int mi = 0; mi < 4; mi++) {                                      \
            uint32_t aoff = (uint32_t)(la_row + mi*16) * GSTRIDE +            \
                            ((ks)*16 + la_k8) * 2;                            \
            ldsm_x4(ahf[fb][mi][0], ahf[fb][mi][1],                           \
                    ahf[fb][mi][2], ahf[fb][mi][3], (base) + aoff);           \
        }                                                                     \
        _Pragma("unroll")                                                     \
        for (int nj = 0; nj < 4; nj++) {                                      \
            uint32_t woff = (uint32_t)(lw_row + nj*16) * GSTRIDE +            \
                            ((ks)*16 + lw_k8) * 2;                            \
            ldsm_x4(whf[fb][nj][0], whf[fb][nj][1],                           \
                    whf[fb][nj][2], whf[fb][nj][3], (base) + G_T + woff);     \
        }                                                                     \
    } while (0)

    LOAD_G(0, 0); CP_COMMIT();
    LOAD_G(1, 1); CP_COMMIT();

    uint32_t ahf[2][4][4], whf[2][4][4];

    for (int kt = 0; kt < NKC; kt++) {
        if (kt + 1 < NKC) CP_WAIT1(); else CP_WAIT0();
        __syncthreads();

        const uint32_t base = smb + (kt & 1) * G_STAGE;
        LOAD_FRAG(0, base, 0);
#pragma unroll
        for (int ks = 0; ks < 4; ks++) {
            const int cur = ks & 1;
            if (ks < 3) LOAD_FRAG(cur ^ 1, base, ks + 1);
#pragma unroll
            for (int mi = 0; mi < 4; mi++)
#pragma unroll
                for (int nf = 0; nf < 8; nf++)
                    mma16816(acc[mi][nf], ahf[cur][mi], &whf[cur][nf >> 1][(nf & 1) * 2]);
        }
        __syncthreads();
        if (kt + 2 < NKC) { LOAD_G(kt & 1, kt + 2); CP_COMMIT(); }
    }

    const int crow  = mbase + warp_m * 64 + (lane >> 2);
    const int ccol0 = nbase + warp_n * 64 + (lane & 3) * 2;
    if constexpr (MODE == 0) {
        __half* O = (z == 0) ? O0 : (z == 1) ? O1 : O2;
        const float scale = (z == 0) ? 0.125f : 1.0f;
#pragma unroll
        for (int nf = 0; nf < 8; nf++) {
            float2 bv = *(const float2*)(bias + ccol0 + nf * 8);
#pragma unroll
            for (int mi = 0; mi < 4; mi++) {
                float* c = acc[mi][nf];
                size_t o0 = (size_t)(crow + mi*16)     * NE + ccol0 + nf*8;
                size_t o1 = (size_t)(crow + mi*16 + 8) * NE + ccol0 + nf*8;
                *(uint32_t*)(O + o0) = pack_h2((c[0] + bv.x) * scale, (c[1] + bv.y) * scale);
                *(uint32_t*)(O + o1) = pack_h2((c[2] + bv.x) * scale, (c[3] + bv.y) * scale);
            }
        }
    } else {
#pragma unroll
        for (int nf = 0; nf < 8; nf++) {
            float2 bv = *(const float2*)(bias + ccol0 + nf * 8);
#pragma unroll
            for (int mi = 0; mi < 4; mi++) {
                float* c = acc[mi][nf];
                *(float2*)(Fout + (size_t)(crow + mi*16)     * NE + ccol0 + nf*8) =
                    make_float2(c[0] * 0.015625f + bv.x, c[1] * 0.015625f + bv.y);
                *(float2*)(Fout + (size_t)(crow + mi*16 + 8) * NE + ccol0 + nf*8) =
                    make_float2(c[2] * 0.015625f + bv.x, c[3] * 0.015625f + bv.y);
            }
        }
    }
#undef LOAD_G
#undef LOAD_FRAG
}

// ---------------------------------------------------------------------------
// Flash attention, 1-term fp16 mma. Unchanged (passing at ~50us).
// ---------------------------------------------------------------------------
#define ARSTRIDE 144
#define ATILE    (64 * ARSTRIDE)       // 9216
#define ASTAGE   (2 * ATILE)           // 18432 : Kh|Vh
#define ASMEM2   (2 * ASTAGE)          // 36864

__global__ void __launch_bounds__(128, 3)
attn_tc()
{
    extern __shared__ char smem[];
    const int tid  = threadIdx.x;
    const int wid  = tid >> 5;
    const int lane = tid & 31;
    const int qt   = (int)gridDim.x - 1 - (int)blockIdx.x;   // heavy first
    const int bh   = blockIdx.y;
    const int b    = bh >> 4;
    const int h    = bh & 15;
    const size_t base = (size_t)b * TSEQ * NE + (size_t)h * DKH;
    const int qb   = qt * 64;
    const uint32_t smb = smem_u32(smem);

#pragma unroll
    for (int i = 0; i < 4; i++) {
        int idx = i * 128 + tid;
        int r = idx >> 3, c = idx & 7;
        *(uint4*)(smem + r * ARSTRIDE + c * 16) =
            *(const uint4*)(g_Qh + base + (size_t)(qb + r) * NE + c * 8);
    }
    __syncthreads();

    const int la_row = wid * 16 + (lane & 15);
    const int la_k8  = ((lane >> 4) & 1) * 8;
    uint32_t qh[4][4];
#pragma unroll
    for (int ks = 0; ks < 4; ks++) {
        uint32_t aoff = (uint32_t)la_row * ARSTRIDE + (ks * 16 + la_k8) * 2;
        ldsm_x4(qh[ks][0], qh[ks][1], qh[ks][2], qh[ks][3], smb + aoff);
    }
    __syncthreads();

    const int lw_row = (lane & 7) + ((lane >> 4) & 1) * 8;
    const int lw_k8  = ((lane >> 3) & 1) * 8;
    const int vt_row = (lane & 7) + ((lane >> 3) & 1) * 8;
    const int vt_cb  = ((lane >> 4) & 1) * 16;

    float m_r[2] = {-1e30f, -1e30f}, l_r[2] = {0.f, 0.f};
    float o[8][4];
#pragma unroll
    for (int nf = 0; nf < 8; nf++)
#pragma unroll
        for (int q = 0; q < 4; q++) o[nf][q] = 0.f;

    const __half* kvp[2] = { g_Kh, g_Vh };

#define LOAD_KV(buf, kt) do {                                                 \
        uint32_t sb_ = smb + (buf) * ASTAGE;                                  \
        int ktb_ = (kt) * 64;                                                 \
        _Pragma("unroll")                                                     \
        for (int i = 0; i < 8; i++) {                                         \
            int id_ = i * 128 + tid;                                          \
            int t2_ = id_ >> 9;                                               \
            int ix_ = id_ & 511;                                              \
            int r_ = ix_ >> 3, c_ = ix_ & 7;                                  \
            const char* src_ = (const char*)(kvp[t2_] + base +                \
                (size_t)(ktb_ + r_) * NE + c_ * 8);                           \
            CP_A16(sb_ + t2_ * ATILE + r_ * ARSTRIDE + c_ * 16, src_);        \
        }                                                                     \
    } while (0)

    const int nkt = qt + 1;
    LOAD_KV(0, 0); CP_COMMIT();
    if (nkt > 1) { LOAD_KV(1, 1); CP_COMMIT(); }

    for (int kt = 0; kt < nkt; kt++) {
        if (kt + 1 < nkt) CP_WAIT1(); else CP_WAIT0();
        __syncthreads();
        const uint32_t sb = smb + (kt & 1) * ASTAGE;

        float s[8][4];
#pragma unroll
        for (int nf = 0; nf < 8; nf++)
#pragma unroll
            for (int q = 0; q < 4; q++) s[nf][q] = 0.f;

#pragma unroll
        for (int ks = 0; ks < 4; ks++) {
            uint32_t kh[4][4];
#pragma unroll
            for (int nj = 0; nj < 4; nj++) {
                uint32_t woff = (uint32_t)(nj * 16 + lw_row) * ARSTRIDE + (ks * 16 + lw_k8) * 2;
                ldsm_x4(kh[nj][0], kh[nj][1], kh[nj][2], kh[nj][3], sb + woff);
            }
#pragma unroll
            for (int nf = 0; nf < 8; nf++)
                mma16816(s[nf], qh[ks], &kh[nf >> 1][(nf & 1) * 2]);
        }

        if (kt == nkt - 1) {
            const int rl0 = wid * 16 + (lane >> 2);
#pragma unroll
            for (int nf = 0; nf < 8; nf++) {
                int cl = nf * 8 + (lane & 3) * 2;
                if (cl     > rl0)     s[nf][0] = -1e30f;
                if (cl + 1 > rl0)     s[nf][1] = -1e30f;
                if (cl     > rl0 + 8) s[nf][2] = -1e30f;
                if (cl + 1 > rl0 + 8) s[nf][3] = -1e30f;
            }
        }

        float corr[2];
#pragma unroll
        for (int r = 0; r < 2; r++) {
            float mx = -1e30f;
#pragma unroll
            for (int nf = 0; nf < 8; nf++)
                mx = fmaxf(mx, fmaxf(s[nf][2*r], s[nf][2*r + 1]));
            mx = fmaxf(mx, __shfl_xor_sync(0xffffffffu, mx, 1));
            mx = fmaxf(mx, __shfl_xor_sync(0xffffffffu, mx, 2));
            float mnew = fmaxf(m_r[r], mx);
            corr[r] = __expf(m_r[r] - mnew);
            float ps = 0.f;
#pragma unroll
            for (int nf = 0; nf < 8; nf++) {
                float p0 = __expf(s[nf][2*r]     - mnew);
                float p1 = __expf(s[nf][2*r + 1] - mnew);
                s[nf][2*r] = p0; s[nf][2*r + 1] = p1;
                ps += p0 + p1;
            }
            ps += __shfl_xor_sync(0xffffffffu, ps, 1);
            ps += __shfl_xor_sync(0xffffffffu, ps, 2);
            l_r[r] = l_r[r] * corr[r] + ps;
            m_r[r] = mnew;
        }
#pragma unroll
        for (int nf = 0; nf < 8; nf++) {
            o[nf][0] *= corr[0]; o[nf][1] *= corr[0];
            o[nf][2] *= corr[1]; o[nf][3] *= corr[1];
        }

#pragma unroll
        for (int ks2 = 0; ks2 < 4; ks2++) {
            uint32_t pa_h[4];
            pa_h[0] = pack_h2(s[2*ks2][0],     s[2*ks2][1]);
            pa_h[1] = pack_h2(s[2*ks2][2],     s[2*ks2][3]);
            pa_h[2] = pack_h2(s[2*ks2 + 1][0], s[2*ks2 + 1][1]);
            pa_h[3] = pack_h2(s[2*ks2 + 1][2], s[2*ks2 + 1][3]);

            uint32_t vh[4][4];
#pragma unroll
            for (int df = 0; df < 4; df++) {
                uint32_t voff = (uint32_t)(ks2 * 16 + vt_row) * ARSTRIDE + df * 32 + vt_cb;
                ldsm_x4_t(vh[df][0], vh[df][1], vh[df][2], vh[df][3], sb + ATILE + voff);
            }
#pragma unroll
            for (int nf = 0; nf < 8; nf++)
                mma16816(o[nf], pa_h, &vh[nf >> 1][(nf & 1) * 2]);
        }
        __syncthreads();
        if (kt + 2 < nkt) { LOAD_KV(kt & 1, kt + 2); CP_COMMIT(); }
    }

    // normalize, scale by 64, store Yh
    const float inv0 = 64.f / l_r[0];
    const float inv1 = 64.f / l_r[1];
    const int grow = qb + wid * 16 + (lane >> 2);
    const int d0 = (lane & 3) * 2;
#pragma unroll
    for (int nf = 0; nf < 8; nf++) {
        size_t p0 = base + (size_t)grow * NE + nf * 8 + d0;
        size_t p1 = base + (size_t)(grow + 8) * NE + nf * 8 + d0;
        *(uint32_t*)(g_Yh + p0) = pack_h2(o[nf][0] * inv0, o[nf][1] * inv0);
        *(uint32_t*)(g_Yh + p1) = pack_h2(o[nf][2] * inv1, o[nf][3] * inv1);
    }
#undef LOAD_KV
}

// ---------------------------------------------------------------------------
extern "C" void kernel_launch(void* const* d_in, const int* in_sizes, int n_in,
                              void* d_out, int out_size)
{
    const float* x  = (const float*)d_in[0];
    const float* Wq = (const float*)d_in[1];
    const float* bq = (const float*)d_in[2];
    const float* Wk = (const float*)d_in[3];
    const float* bk = (const float*)d_in[4];
    const float* Wv = (const float*)d_in[5];
    const float* bv = (const float*)d_in[6];
    const float* Wo = (const float*)d_in[7];
    const float* bo = (const float*)d_in[8];
    float* out = (float*)d_out;

    __half *Xh, *WhB, *Qh, *Kh, *Vh, *Yh;
    cudaGetSymbolAddress((void**)&Xh, g_Xh);
    cudaGetSymbolAddress((void**)&WhB, g_Wh);
    cudaGetSymbolAddress((void**)&Qh, g_Qh);
    cudaGetSymbolAddress((void**)&Kh, g_Kh);
    cudaGetSymbolAddress((void**)&Vh, g_Vh);
    cudaGetSymbolAddress((void**)&Yh, g_Yh);

    static bool attr_done = false;
    if (!attr_done) {
        cudaFuncSetAttribute(gemm64<0>, cudaFuncAttributeMaxDynamicSharedMemorySize, GSMEM);
        cudaFuncSetAttribute(gemm64<1>, cudaFuncAttributeMaxDynamicSharedMemorySize, GSMEM);
        attr_done = true;
    }

    // fused pre-pass: x -> Xh, weights -> Wh
    split_all<<<8192, 256>>>(x, Wq, Wk, Wv, Wo, Xh, WhB);

    // QKV projections (1-term, fp16 outputs, Q pre-scaled by 0.125)
    gemm64<0><<<dim3(8, 32, 3), 128, GSMEM>>>(Xh, WhB, bq, bk, bv, Qh, Kh, Vh, nullptr);
    // attention (1-term S and PV, Y = 64*O fp16)
    attn_tc<<<dim3(32, 32), 128, ASMEM2>>>();
    // output projection (1-term, fp32 out, undoes the 64x)
    gemm64<1><<<dim3(8, 32, 1), 128, GSMEM>>>(Yh, WhB + 3*(size_t)NE*NE, bo, bo, bo,
                                              nullptr, nullptr, nullptr, out);
}

// round 14
// speedup vs baseline: 1.0144x; 1.0144x over previous
#include <cuda_runtime.h>
#include <cuda_fp16.h>
#include <cstdint>
#include <math.h>

#define TSEQ 2048
#define NE   1024
#define NH   16
#define DKH  64
#define NB   2
#define MTOT (NB*TSEQ)   // 4096

// Scratch (allocation-free), fp16.
__device__ __half g_Xh[MTOT*NE];
__device__ __half g_Wh[4*NE*NE];    // q,k,v,o
__device__ __half g_Qh[MTOT*NE];    // Q pre-scaled by 0.125
__device__ __half g_Kh[MTOT*NE];
__device__ __half g_Vh[MTOT*NE];
__device__ __half g_Yh[MTOT*NE];    // attention out, pre-scaled by 64

// ---------------------------------------------------------------------------
static __device__ __forceinline__ uint32_t smem_u32(const void* p) {
    uint32_t a;
    asm("{ .reg .u64 t; cvta.to.shared.u64 t, %1; cvt.u32.u64 %0, t; }" : "=r"(a) : "l"(p));
    return a;
}
static __device__ __forceinline__ void ldsm_x4(uint32_t& r0, uint32_t& r1,
                                               uint32_t& r2, uint32_t& r3, uint32_t a) {
    asm volatile("ldmatrix.sync.aligned.m8n8.x4.shared.b16 {%0,%1,%2,%3}, [%4];"
                 : "=r"(r0), "=r"(r1), "=r"(r2), "=r"(r3) : "r"(a));
}
static __device__ __forceinline__ void ldsm_x4_t(uint32_t& r0, uint32_t& r1,
                                                 uint32_t& r2, uint32_t& r3, uint32_t a) {
    asm volatile("ldmatrix.sync.aligned.m8n8.x4.trans.shared.b16 {%0,%1,%2,%3}, [%4];"
                 : "=r"(r0), "=r"(r1), "=r"(r2), "=r"(r3) : "r"(a));
}
static __device__ __forceinline__ void mma16816(float* c, const uint32_t* a, const uint32_t* b) {
    asm volatile("mma.sync.aligned.m16n8k16.row.col.f32.f16.f16.f32 "
                 "{%0,%1,%2,%3}, {%4,%5,%6,%7}, {%8,%9}, {%0,%1,%2,%3};"
                 : "+f"(c[0]), "+f"(c[1]), "+f"(c[2]), "+f"(c[3])
                 : "r"(a[0]), "r"(a[1]), "r"(a[2]), "r"(a[3]), "r"(b[0]), "r"(b[1]));
}
#define CP_A16(dst, src) asm volatile("cp.async.cg.shared.global [%0], [%1], 16;" :: "r"(dst), "l"(src))
#define CP_COMMIT()      asm volatile("cp.async.commit_group;" ::: "memory")
#define CP_WAIT0()       asm volatile("cp.async.wait_group 0;" ::: "memory")
#define CP_WAIT1()       asm volatile("cp.async.wait_group 1;" ::: "memory")

static __device__ __forceinline__ uint32_t pack_h2(float x, float y) {
    union { __half2 b; uint32_t u; } p;
    p.b.x = __float2half_rn(x); p.b.y = __float2half_rn(y);
    return p.u;
}

// ---------------------------------------------------------------------------
// Fused pre-pass: x -> Xh; Wq,k,v,o -> Wh.
// ---------------------------------------------------------------------------
__global__ void split_all(const float* __restrict__ x,
                          const float* __restrict__ Wq, const float* __restrict__ Wk,
                          const float* __restrict__ Wv, const float* __restrict__ Wo,
                          __half* __restrict__ Xh, __half* __restrict__ WhB)
{
    const int bx = blockIdx.x;
    if (bx < 4096) {
        size_t i = (size_t)bx * 1024 + threadIdx.x * 4;
        float4 v = *(const float4*)(x + i);
        *(uint2*)(Xh + i) = make_uint2(pack_h2(v.x, v.y), pack_h2(v.z, v.w));
    } else {
        const int r = bx - 4096;
        const int w = r >> 10;
        const float* ws = (w == 0) ? Wq : (w == 1) ? Wk : (w == 2) ? Wv : Wo;
        size_t j = (size_t)(r & 1023) * 1024 + threadIdx.x * 4;
        float4 v = *(const float4*)(ws + j);
        *(uint2*)(WhB + (size_t)w * NE * NE + j) =
            make_uint2(pack_h2(v.x, v.y), pack_h2(v.z, v.w));
    }
}

// ---------------------------------------------------------------------------
// GEMM: C = A * Wh^T (1 term). CTA 128x256, 256 threads (8 warps, 2x4 grid,
// warp tile 64x64), kc=64, 2-stage cp.async gmem ring + fragment double-
// buffer, 1 CTA/SM. Row stride 144B -> conflict-free ldsm.
// MODE 0: fp16 out, scale (z==0 ? 0.125 : 1). MODE 1: fp32 out, *1/64 + bias.
// ---------------------------------------------------------------------------
#define GSTRIDE 144
#define G_AT    (128 * GSTRIDE)          // 18432 (A tile)
#define G_WT    (256 * GSTRIDE)          // 36864 (W tile)
#define G_STAGE (G_AT + G_WT)            // 55296
#define GSMEM   (2 * G_STAGE)            // 110592
#define NKC     (NE / 64)                // 16

template<int MODE>
__global__ void __launch_bounds__(256, 1)
gemm64(const __half* __restrict__ Ah, const __half* __restrict__ WhB,
       const float* __restrict__ b0, const float* __restrict__ b1, const float* __restrict__ b2,
       __half* __restrict__ O0, __half* __restrict__ O1, __half* __restrict__ O2,
       float* __restrict__ Fout)
{
    extern __shared__ char smem[];
    const int tid  = threadIdx.x;
    const int wid  = tid >> 5;
    const int lane = tid & 31;
    const int z    = blockIdx.z;
    const __half* Wh = WhB + (size_t)z * NE * NE;
    const float* bias = (z == 0) ? b0 : (z == 1) ? b1 : b2;
    const int mbase = blockIdx.y * 128;
    const int nbase = blockIdx.x * 256;
    const uint32_t smb = smem_u32(smem);

    const int warp_m = wid >> 2;        // 0..1 -> 64 rows
    const int warp_n = wid & 3;         // 0..3 -> 64 cols
    const int la_row = warp_m * 64 + (lane & 15);
    const int la_k8  = ((lane >> 4) & 1) * 8;
    const int lw_row = warp_n * 64 + (lane & 7) + ((lane >> 4) & 1) * 8;
    const int lw_k8  = ((lane >> 3) & 1) * 8;

    const int lr = tid >> 3;       // 0..31
    const int lc = tid & 7;        // 0..7 -> 16B chunk

    float acc[4][8][4];
#pragma unroll
    for (int mi = 0; mi < 4; mi++)
#pragma unroll
        for (int nf = 0; nf < 8; nf++)
#pragma unroll
            for (int q = 0; q < 4; q++) acc[mi][nf][q] = 0.f;

#define LOAD_G(buf, kt) do {                                                  \
        uint32_t sb_ = smb + (buf) * G_STAGE;                                 \
        int kcol_ = (kt) * 64 + lc * 8;                                       \
        _Pragma("unroll")                                                     \
        for (int i = 0; i < 4; i++) {                                         \
            int r_ = lr + 32 * i;                                             \
            CP_A16(sb_ + r_ * GSTRIDE + lc * 16,                              \
                   (const char*)(Ah + (size_t)(mbase + r_) * NE + kcol_));    \
        }                                                                     \
        _Pragma("unroll")                                                     \
        for (int i = 0; i < 8; i++) {                                         \
            int r_ = lr + 32 * i;                                             \
            CP_A16(sb_ + G_AT + r_ * GSTRIDE + lc * 16,                       \
                   (const char*)(Wh + (size_t)(nbase + r_) * NE + kcol_));    \
        }                                                                     \
    } while (0)

// Load ldsm fragments for k-slice ks into buffer fb.
#define LOAD_FRAG(fb, base, ks) do {                                          \
        _Pragma("unroll")                                                     \
        for (int mi = 0; mi < 4; mi++) {                                      \
            uint32_t aoff = (uint32_t)(la_row + mi*16) * GSTRIDE +            \
                            ((ks)*16 + la_k8) * 2;                            \
            ldsm_x4(ahf[fb][mi][0], ahf[fb][mi][1],                           \
                    ahf[fb][mi][2], ahf[fb][mi][3], (base) + aoff);           \
        }                                                                     \
        _Pragma("unroll")                                                     \
        for (int nj = 0; nj < 4; nj++) {                                      \
            uint32_t woff = (uint32_t)(lw_row + nj*16) * GSTRIDE +            \
                            ((ks)*16 + lw_k8) * 2;                            \
            ldsm_x4(whf[fb][nj][0], whf[fb][nj][1],                           \
                    whf[fb][nj][2], whf[fb][nj][3], (base) + G_AT + woff);    \
        }                                                                     \
    } while (0)

    LOAD_G(0, 0); CP_COMMIT();
    LOAD_G(1, 1); CP_COMMIT();

    uint32_t ahf[2][4][4], whf[2][4][4];

    for (int kt = 0; kt < NKC; kt++) {
        if (kt + 1 < NKC) CP_WAIT1(); else CP_WAIT0();
        __syncthreads();

        const uint32_t base = smb + (kt & 1) * G_STAGE;
        LOAD_FRAG(0, base, 0);
#pragma unroll
        for (int ks = 0; ks < 4; ks++) {
            const int cur = ks & 1;
            if (ks < 3) LOAD_FRAG(cur ^ 1, base, ks + 1);
#pragma unroll
            for (int mi = 0; mi < 4; mi++)
#pragma unroll
                for (int nf = 0; nf < 8; nf++)
                    mma16816(acc[mi][nf], ahf[cur][mi], &whf[cur][nf >> 1][(nf & 1) * 2]);
        }
        __syncthreads();
        if (kt + 2 < NKC) { LOAD_G(kt & 1, kt + 2); CP_COMMIT(); }
    }

    const int crow  = mbase + warp_m * 64 + (lane >> 2);
    const int ccol0 = nbase + warp_n * 64 + (lane & 3) * 2;
    if constexpr (MODE == 0) {
        __half* O = (z == 0) ? O0 : (z == 1) ? O1 : O2;
        const float scale = (z == 0) ? 0.125f : 1.0f;
#pragma unroll
        for (int nf = 0; nf < 8; nf++) {
            float2 bv = *(const float2*)(bias + ccol0 + nf * 8);
#pragma unroll
            for (int mi = 0; mi < 4; mi++) {
                float* c = acc[mi][nf];
                size_t o0 = (size_t)(crow + mi*16)     * NE + ccol0 + nf*8;
                size_t o1 = (size_t)(crow + mi*16 + 8) * NE + ccol0 + nf*8;
                *(uint32_t*)(O + o0) = pack_h2((c[0] + bv.x) * scale, (c[1] + bv.y) * scale);
                *(uint32_t*)(O + o1) = pack_h2((c[2] + bv.x) * scale, (c[3] + bv.y) * scale);
            }
        }
    } else {
#pragma unroll
        for (int nf = 0; nf < 8; nf++) {
            float2 bv = *(const float2*)(bias + ccol0 + nf * 8);
#pragma unroll
            for (int mi = 0; mi < 4; mi++) {
                float* c = acc[mi][nf];
                *(float2*)(Fout + (size_t)(crow + mi*16)     * NE + ccol0 + nf*8) =
                    make_float2(c[0] * 0.015625f + bv.x, c[1] * 0.015625f + bv.y);
                *(float2*)(Fout + (size_t)(crow + mi*16 + 8) * NE + ccol0 + nf*8) =
                    make_float2(c[2] * 0.015625f + bv.x, c[3] * 0.015625f + bv.y);
            }
        }
    }
#undef LOAD_G
#undef LOAD_FRAG
}

// ---------------------------------------------------------------------------
// Flash attention, 1-term fp16 mma. Unchanged (passing, ~50us).
// ---------------------------------------------------------------------------
#define ARSTRIDE 144
#define ATILE    (64 * ARSTRIDE)       // 9216
#define ASTAGE   (2 * ATILE)           // 18432 : Kh|Vh
#define ASMEM2   (2 * ASTAGE)          // 36864

__global__ void __launch_bounds__(128, 3)
attn_tc()
{
    extern __shared__ char smem[];
    const int tid  = threadIdx.x;
    const int wid  = tid >> 5;
    const int lane = tid & 31;
    const int qt   = (int)gridDim.x - 1 - (int)blockIdx.x;   // heavy first
    const int bh   = blockIdx.y;
    const int b    = bh >> 4;
    const int h    = bh & 15;
    const size_t base = (size_t)b * TSEQ * NE + (size_t)h * DKH;
    const int qb   = qt * 64;
    const uint32_t smb = smem_u32(smem);

#pragma unroll
    for (int i = 0; i < 4; i++) {
        int idx = i * 128 + tid;
        int r = idx >> 3, c = idx & 7;
        *(uint4*)(smem + r * ARSTRIDE + c * 16) =
            *(const uint4*)(g_Qh + base + (size_t)(qb + r) * NE + c * 8);
    }
    __syncthreads();

    const int la_row = wid * 16 + (lane & 15);
    const int la_k8  = ((lane >> 4) & 1) * 8;
    uint32_t qh[4][4];
#pragma unroll
    for (int ks = 0; ks < 4; ks++) {
        uint32_t aoff = (uint32_t)la_row * ARSTRIDE + (ks * 16 + la_k8) * 2;
        ldsm_x4(qh[ks][0], qh[ks][1], qh[ks][2], qh[ks][3], smb + aoff);
    }
    __syncthreads();

    const int lw_row = (lane & 7) + ((lane >> 4) & 1) * 8;
    const int lw_k8  = ((lane >> 3) & 1) * 8;
    const int vt_row = (lane & 7) + ((lane >> 3) & 1) * 8;
    const int vt_cb  = ((lane >> 4) & 1) * 16;

    float m_r[2] = {-1e30f, -1e30f}, l_r[2] = {0.f, 0.f};
    float o[8][4];
#pragma unroll
    for (int nf = 0; nf < 8; nf++)
#pragma unroll
        for (int q = 0; q < 4; q++) o[nf][q] = 0.f;

    const __half* kvp[2] = { g_Kh, g_Vh };

#define LOAD_KV(buf, kt) do {                                                 \
        uint32_t sb_ = smb + (buf) * ASTAGE;                                  \
        int ktb_ = (kt) * 64;                                                 \
        _Pragma("unroll")                                                     \
        for (int i = 0; i < 8; i++) {                                         \
            int id_ = i * 128 + tid;                                          \
            int t2_ = id_ >> 9;                                               \
            int ix_ = id_ & 511;                                              \
            int r_ = ix_ >> 3, c_ = ix_ & 7;                                  \
            const char* src_ = (const char*)(kvp[t2_] + base +                \
                (size_t)(ktb_ + r_) * NE + c_ * 8);                           \
            CP_A16(sb_ + t2_ * ATILE + r_ * ARSTRIDE + c_ * 16, src_);        \
        }                                                                     \
    } while (0)

    const int nkt = qt + 1;
    LOAD_KV(0, 0); CP_COMMIT();
    if (nkt > 1) { LOAD_KV(1, 1); CP_COMMIT(); }

    for (int kt = 0; kt < nkt; kt++) {
        if (kt + 1 < nkt) CP_WAIT1(); else CP_WAIT0();
        __syncthreads();
        const uint32_t sb = smb + (kt & 1) * ASTAGE;

        float s[8][4];
#pragma unroll
        for (int nf = 0; nf < 8; nf++)
#pragma unroll
            for (int q = 0; q < 4; q++) s[nf][q] = 0.f;

#pragma unroll
        for (int ks = 0; ks < 4; ks++) {
            uint32_t kh[4][4];
#pragma unroll
            for (int nj = 0; nj < 4; nj++) {
                uint32_t woff = (uint32_t)(nj * 16 + lw_row) * ARSTRIDE + (ks * 16 + lw_k8) * 2;
                ldsm_x4(kh[nj][0], kh[nj][1], kh[nj][2], kh[nj][3], sb + woff);
            }
#pragma unroll
            for (int nf = 0; nf < 8; nf++)
                mma16816(s[nf], qh[ks], &kh[nf >> 1][(nf & 1) * 2]);
        }

        if (kt == nkt - 1) {
            const int rl0 = wid * 16 + (lane >> 2);
#pragma unroll
            for (int nf = 0; nf < 8; nf++) {
                int cl = nf * 8 + (lane & 3) * 2;
                if (cl     > rl0)     s[nf][0] = -1e30f;
                if (cl + 1 > rl0)     s[nf][1] = -1e30f;
                if (cl     > rl0 + 8) s[nf][2] = -1e30f;
                if (cl + 1 > rl0 + 8) s[nf][3] = -1e30f;
            }
        }

        float corr[2];
#pragma unroll
        for (int r = 0; r < 2; r++) {
            float mx = -1e30f;
#pragma unroll
            for (int nf = 0; nf < 8; nf++)
                mx = fmaxf(mx, fmaxf(s[nf][2*r], s[nf][2*r + 1]));
            mx = fmaxf(mx, __shfl_xor_sync(0xffffffffu, mx, 1));
            mx = fmaxf(mx, __shfl_xor_sync(0xffffffffu, mx, 2));
            float mnew = fmaxf(m_r[r], mx);
            corr[r] = __expf(m_r[r] - mnew);
            float ps = 0.f;
#pragma unroll
            for (int nf = 0; nf < 8; nf++) {
                float p0 = __expf(s[nf][2*r]     - mnew);
                float p1 = __expf(s[nf][2*r + 1] - mnew);
                s[nf][2*r] = p0; s[nf][2*r + 1] = p1;
                ps += p0 + p1;
            }
            ps += __shfl_xor_sync(0xffffffffu, ps, 1);
            ps += __shfl_xor_sync(0xffffffffu, ps, 2);
            l_r[r] = l_r[r] * corr[r] + ps;
            m_r[r] = mnew;
        }
#pragma unroll
        for (int nf = 0; nf < 8; nf++) {
            o[nf][0] *= corr[0]; o[nf][1] *= corr[0];
            o[nf][2] *= corr[1]; o[nf][3] *= corr[1];
        }

#pragma unroll
        for (int ks2 = 0; ks2 < 4; ks2++) {
            uint32_t pa_h[4];
            pa_h[0] = pack_h2(s[2*ks2][0],     s[2*ks2][1]);
            pa_h[1] = pack_h2(s[2*ks2][2],     s[2*ks2][3]);
            pa_h[2] = pack_h2(s[2*ks2 + 1][0], s[2*ks2 + 1][1]);
            pa_h[3] = pack_h2(s[2*ks2 + 1][2], s[2*ks2 + 1][3]);

            uint32_t vh[4][4];
#pragma unroll
            for (int df = 0; df < 4; df++) {
                uint32_t voff = (uint32_t)(ks2 * 16 + vt_row) * ARSTRIDE + df * 32 + vt_cb;
                ldsm_x4_t(vh[df][0], vh[df][1], vh[df][2], vh[df][3], sb + ATILE + voff);
            }
#pragma unroll
            for (int nf = 0; nf < 8; nf++)
                mma16816(o[nf], pa_h, &vh[nf >> 1][(nf & 1) * 2]);
        }
        __syncthreads();
        if (kt + 2 < nkt) { LOAD_KV(kt & 1, kt + 2); CP_COMMIT(); }
    }

    // normalize, scale by 64, store Yh
    const float inv0 = 64.f / l_r[0];
    const float inv1 = 64.f / l_r[1];
    const int grow = qb + wid * 16 + (lane >> 2);
    const int d0 = (lane & 3) * 2;
#pragma unroll
    for (int nf = 0; nf < 8; nf++) {
        size_t p0 = base + (size_t)grow * NE + nf * 8 + d0;
        size_t p1 = base + (size_t)(grow + 8) * NE + nf * 8 + d0;
        *(uint32_t*)(g_Yh + p0) = pack_h2(o[nf][0] * inv0, o[nf][1] * inv0);
        *(uint32_t*)(g_Yh + p1) = pack_h2(o[nf][2] * inv1, o[nf][3] * inv1);
    }
#undef LOAD_KV
}

// ---------------------------------------------------------------------------
extern "C" void kernel_launch(void* const* d_in, const int* in_sizes, int n_in,
                              void* d_out, int out_size)
{
    const float* x  = (const float*)d_in[0];
    const float* Wq = (const float*)d_in[1];
    const float* bq = (const float*)d_in[2];
    const float* Wk = (const float*)d_in[3];
    const float* bk = (const float*)d_in[4];
    const float* Wv = (const float*)d_in[5];
    const float* bv = (const float*)d_in[6];
    const float* Wo = (const float*)d_in[7];
    const float* bo = (const float*)d_in[8];
    float* out = (float*)d_out;

    __half *Xh, *WhB, *Qh, *Kh, *Vh, *Yh;
    cudaGetSymbolAddress((void**)&Xh, g_Xh);
    cudaGetSymbolAddress((void**)&WhB, g_Wh);
    cudaGetSymbolAddress((void**)&Qh, g_Qh);
    cudaGetSymbolAddress((void**)&Kh, g_Kh);
    cudaGetSymbolAddress((void**)&Vh, g_Vh);
    cudaGetSymbolAddress((void**)&Yh, g_Yh);

    static bool attr_done = false;
    if (!attr_done) {
        cudaFuncSetAttribute(gemm64<0>, cudaFuncAttributeMaxDynamicSharedMemorySize, GSMEM);
        cudaFuncSetAttribute(gemm64<1>, cudaFuncAttributeMaxDynamicSharedMemorySize, GSMEM);
        attr_done = true;
    }

    // fused pre-pass: x -> Xh, weights -> Wh
    split_all<<<8192, 256>>>(x, Wq, Wk, Wv, Wo, Xh, WhB);

    // QKV projections (1-term, fp16 outputs, Q pre-scaled by 0.125)
    gemm64<0><<<dim3(4, 32, 3), 256, GSMEM>>>(Xh, WhB, bq, bk, bv, Qh, Kh, Vh, nullptr);
    // attention (1-term S and PV, Y = 64*O fp16)
    attn_tc<<<dim3(32, 32), 128, ASMEM2>>>();
    // output projection (1-term, fp32 out, undoes the 64x)
    gemm64<1><<<dim3(4, 32, 1), 256, GSMEM>>>(Yh, WhB + 3*(size_t)NE*NE, bo, bo, bo,
                                              nullptr, nullptr, nullptr, out);
}